// round 16
// baseline (speedup 1.0000x reference)
#include <cuda_runtime.h>
#include <cuda_bf16.h>
#include <cstdint>

#define N_TOTAL   32768
#define K_CODES   8192
#define C_DIM     256
#define S_SPATIAL 4096
#define CS        (C_DIM * S_SPATIAL)
#define OUT_Z_ELEMS 8388608

#define M_CTA   256
#define NCH     32
#define TAU     2.0e-4f
#define ROWPAD  264
#define BBYTES  16896                // 32 codes * 528 B

// dynamic smem map (bytes)
#define SM_CNS   0                   // float[4][32]  (group*2+buf)
#define SM_A     1024                // 256 * 528 = 135168
#define SM_B     (SM_A + 135168)     // 4 buffers of 16896 = 67584
#define SMEM_BYTES (SM_B + 4 * BBYTES)   // 203776

// resolve-phase smem layout (reuses dead A region)
#define RS_AMBN   (SM_A + 0)
#define RS_FSN    (SM_A + 4)
#define RS_FSROW  (SM_A + 16)                 // int[256]
#define RS_AMBROW (SM_A + 1040)               // int[256]
#define RS_AMBCNT (SM_A + 2064)               // int[256]
#define RS_AMBCAND (SM_A + 3088)              // int[256*16]
#define RS_ZROW   (SM_A + 19472)              // float[256]
#define RS_RS     (SM_A + 20496)              // float[512]
#define RS_RI     (SM_A + 22544)              // int[512]

__device__ float g_znorm[N_TOTAL];
__device__ float g_cnorm[K_CODES];
__device__ int   g_idx[N_TOTAL];
__device__ __align__(16) __nv_bfloat16 g_cb16[K_CODES * C_DIM];

// ---------- PTX helpers ----------
__device__ __forceinline__ uint32_t smem_u32(const void* p) {
    uint32_t a;
    asm("{ .reg .u64 t; cvta.to.shared.u64 t, %1; cvt.u32.u64 %0, t; }" : "=r"(a) : "l"(p));
    return a;
}
__device__ __forceinline__ void ldmx4(uint32_t* r, uint32_t addr) {
    asm volatile("ldmatrix.sync.aligned.m8n8.x4.shared.b16 {%0,%1,%2,%3}, [%4];"
                 : "=r"(r[0]), "=r"(r[1]), "=r"(r[2]), "=r"(r[3]) : "r"(addr));
}
__device__ __forceinline__ void mma16816(float* d, const uint32_t* a,
                                         uint32_t b0, uint32_t b1) {
    asm volatile("mma.sync.aligned.m16n8k16.row.col.f32.bf16.bf16.f32 "
                 "{%0,%1,%2,%3}, {%4,%5,%6,%7}, {%8,%9}, {%0,%1,%2,%3};"
                 : "+f"(d[0]), "+f"(d[1]), "+f"(d[2]), "+f"(d[3])
                 : "r"(a[0]), "r"(a[1]), "r"(a[2]), "r"(a[3]), "r"(b0), "r"(b1));
}
__device__ __forceinline__ void cpasync16(uint32_t dst, const void* src) {
    asm volatile("cp.async.ca.shared.global [%0], [%1], 16;" :: "r"(dst), "l"(src));
}
__device__ __forceinline__ void barsync(int id, int cnt) {
    asm volatile("bar.sync %0, %1;" :: "r"(id), "r"(cnt) : "memory");
}

// ---------- prep: loss init + norms + bf16 codebook, one kernel ----------
__global__ void prep_kernel(const float* __restrict__ z, const float* __restrict__ cb,
                            float* __restrict__ loss) {
    int bid = blockIdx.x, tid = threadIdx.x;
    if (bid < 256) {
        int n0 = bid * 128, b = n0 >> 12, s0 = n0 & 4095;
        const float* zr = z + (size_t)b * CS + s0 + tid;
        float sum = 0.0f;
        #pragma unroll 8
        for (int c = 0; c < C_DIM; c++) { float v = zr[(size_t)c * S_SPATIAL]; sum += v * v; }
        g_znorm[n0 + tid] = sum;
    } else if (bid < 320) {
        if (bid == 256 && tid == 0) *loss = 0.0f;
        int k = (bid - 256) * 128 + tid;
        const float4* cr = (const float4*)(cb + (size_t)k * C_DIM);
        float sum = 0.0f;
        #pragma unroll 8
        for (int i = 0; i < C_DIM / 4; i++) {
            float4 v = cr[i];
            sum += v.x * v.x + v.y * v.y + v.z * v.z + v.w * v.w;
        }
        g_cnorm[k] = sum;
    } else {
        int base = (bid - 320) * 4096;
        #pragma unroll 8
        for (int k = 0; k < 32; k++) {
            int i = base + k * 128 + tid;
            g_cb16[i] = __float2bfloat16_rn(cb[i]);
        }
    }
}

// ---------- main: GEMM argmin + inline exact resolution ----------
__global__ void __launch_bounds__(512, 1)
argmin_mma_kernel(const float* __restrict__ z, const float* __restrict__ cb,
                  float* __restrict__ out_idx_f) {
    extern __shared__ char sm[];
    uint32_t smb = smem_u32(sm);
    int tid = threadIdx.x;
    int w = tid >> 5, l = tid & 31;
    int g  = w >> 3;
    int wm = w & 7;
    int gl = tid & 255;
    int n0 = blockIdx.x * M_CTA;
    int b = n0 >> 12, s0 = n0 & 4095;
    float* cns = (float*)(sm + SM_CNS);

    // ---- fill A ----
    {
        __nv_bfloat16* A = (__nv_bfloat16*)(sm + SM_A);
        int row = tid & 255;
        int ch0 = (tid >> 8) * 128;
        const float* zp = z + (size_t)b * CS + s0 + row;
        #pragma unroll 4
        for (int c = ch0; c < ch0 + 128; c += 2) {
            float v0 = zp[(size_t)c << 12];
            float v1 = zp[(size_t)(c + 1) << 12];
            __nv_bfloat162 pk;
            pk.x = __float2bfloat16_rn(v0);
            pk.y = __float2bfloat16_rn(v1);
            *(__nv_bfloat162*)&A[row * ROWPAD + c] = pk;
        }
    }

    float zn4[4];
    #pragma unroll
    for (int s = 0; s < 4; s++)
        zn4[s] = g_znorm[n0 + wm * 32 + (s >> 1) * 16 + (s & 1) * 8 + (l >> 2)];

    uint32_t aoff0 = smb + SM_A + (uint32_t)((wm * 32 + (l & 15)) * 528 + (l >> 4) * 16);
    uint32_t aoff1 = aoff0 + 16u * 528u;
    uint32_t bbase = smb + SM_B + (uint32_t)(g * 2 * BBYTES);
    uint32_t bofs0 = (uint32_t)((l & 15) * 528 + (l >> 4) * 16);
    uint32_t bofs1 = bofs0 + 16u * 528u;

    float bS[4][4]; int bI[4][4];
    #pragma unroll
    for (int s = 0; s < 4; s++)
        #pragma unroll
        for (int k = 0; k < 4; k++) { bS[s][k] = 3.4e38f; bI[s][k] = 0; }

    auto stage = [&](int k) {
        int chunk = g + 2 * k;
        const __nv_bfloat16* src = g_cb16 + (size_t)chunk * NCH * C_DIM;
        uint32_t bb = bbase + (uint32_t)((k & 1) * BBYTES);
        #pragma unroll
        for (int t = 0; t < 4; t++) {
            int idx = t * 256 + gl;
            int code = idx >> 5, seg = idx & 31;
            cpasync16(bb + (uint32_t)(code * 528 + seg * 16),
                      src + (size_t)code * C_DIM + seg * 8);
        }
        if (gl < NCH) cns[(g * 2 + (k & 1)) * NCH + gl] = g_cnorm[chunk * NCH + gl];
        asm volatile("cp.async.commit_group;" ::: "memory");
    };

    stage(0);
    stage(1);
    __syncthreads();

    int barid = g + 1;
    for (int k = 0; k < 128; k++) {
        if (k < 126) { asm volatile("cp.async.wait_group 1;" ::: "memory"); }
        else         { asm volatile("cp.async.wait_group 0;" ::: "memory"); }
        barsync(barid, 256);

        float acc[2][4][4];
        #pragma unroll
        for (int mt = 0; mt < 2; mt++)
            #pragma unroll
            for (int nt = 0; nt < 4; nt++)
                #pragma unroll
                for (int c = 0; c < 4; c++) acc[mt][nt][c] = 0.0f;

        uint32_t bsel = bbase + (uint32_t)((k & 1) * BBYTES);
        uint32_t aF[2][2][4], bF[2][2][4];
        ldmx4(aF[0][0], aoff0);
        ldmx4(aF[0][1], aoff1);
        ldmx4(bF[0][0], bsel + bofs0);
        ldmx4(bF[0][1], bsel + bofs1);
        #pragma unroll
        for (int ks = 0; ks < 16; ks++) {
            int cur = ks & 1, nxt = cur ^ 1;
            if (ks < 15) {
                uint32_t ka = (uint32_t)((ks + 1) * 32);
                ldmx4(aF[nxt][0], aoff0 + ka);
                ldmx4(aF[nxt][1], aoff1 + ka);
                ldmx4(bF[nxt][0], bsel + bofs0 + ka);
                ldmx4(bF[nxt][1], bsel + bofs1 + ka);
            }
            #pragma unroll
            for (int p = 0; p < 2; p++) {
                mma16816(acc[0][2 * p],     aF[cur][0], bF[cur][p][0], bF[cur][p][2]);
                mma16816(acc[0][2 * p + 1], aF[cur][0], bF[cur][p][1], bF[cur][p][3]);
                mma16816(acc[1][2 * p],     aF[cur][1], bF[cur][p][0], bF[cur][p][2]);
                mma16816(acc[1][2 * p + 1], aF[cur][1], bF[cur][p][1], bF[cur][p][3]);
            }
        }

        const float* cn = cns + (g * 2 + (k & 1)) * NCH;
        int j0 = (g + 2 * k) * NCH;
        #pragma unroll
        for (int nt = 0; nt < 4; nt++) {
            int col0 = nt * 8 + 2 * (l & 3);
            float2 cn2 = *(const float2*)&cn[col0];
            int id0 = j0 + col0;
            #pragma unroll
            for (int mt = 0; mt < 2; mt++) {
                #pragma unroll
                for (int c = 0; c < 4; c++) {
                    int slot = mt * 2 + (c >> 1);
                    float base = zn4[slot] + ((c & 1) ? cn2.y : cn2.x);
                    float s = fmaf(-2.0f, acc[mt][nt][c], base);
                    if (s < bS[slot][3]) {
                        int id = id0 + (c & 1);
                        #pragma unroll
                        for (int kk = 0; kk < 4; kk++) {
                            if (s < bS[slot][kk]) {
                                float ts = bS[slot][kk]; int ti = bI[slot][kk];
                                bS[slot][kk] = s; bI[slot][kk] = id;
                                s = ts; id = ti;
                            }
                        }
                    }
                }
            }
        }

        barsync(barid, 256);
        if (k + 2 < 128) stage(k + 2);
    }

    // ---- merge: per row 32 entries in SM_B region ----
    float* mergeS = (float*)(sm + SM_B);
    int*   mergeI = (int*)(sm + SM_B + 32768);
    __syncthreads();
    if (tid == 0) { *(int*)(sm + RS_AMBN) = 0; *(int*)(sm + RS_FSN) = 0; }
    #pragma unroll
    for (int s = 0; s < 4; s++) {
        int row = wm * 32 + (s >> 1) * 16 + (s & 1) * 8 + (l >> 2);
        int base = row * 32 + g * 16 + (l & 3) * 4;
        #pragma unroll
        for (int k = 0; k < 4; k++) { mergeS[base + k] = bS[s][k]; mergeI[base + k] = bI[s][k]; }
    }
    __syncthreads();

    // ---- classify ----
    int* ambN    = (int*)(sm + RS_AMBN);
    int* fsN     = (int*)(sm + RS_FSN);
    int* fsRow   = (int*)(sm + RS_FSROW);
    int* ambRow  = (int*)(sm + RS_AMBROW);
    int* ambCnt  = (int*)(sm + RS_AMBCNT);
    int* ambCand = (int*)(sm + RS_AMBCAND);
    if (tid < 256) {
        int base = tid * 32;
        float mn = 3.4e38f;
        #pragma unroll
        for (int k = 0; k < 32; k++) mn = fminf(mn, mergeS[base + k]);
        float lim = mn + TAU;
        bool fs = false;
        #pragma unroll
        for (int q = 0; q < 8; q++) if (mergeS[base + q * 4 + 3] <= lim) fs = true;
        int cnt = 0; float bs = 3.4e38f; int bi = 0x7fffffff;
        #pragma unroll
        for (int k = 0; k < 32; k++) {
            float s = mergeS[base + k]; int id = mergeI[base + k];
            if (s <= lim) cnt++;
            if (s < bs || (s == bs && id < bi)) { bs = s; bi = id; }
        }
        if (cnt > 16) fs = true;
        if (fs) {
            int p = atomicAdd(fsN, 1);
            fsRow[p] = tid;
        } else if (cnt == 1) {
            g_idx[n0 + tid] = bi;
            out_idx_f[n0 + tid] = (float)bi;
        } else {
            int p = atomicAdd(ambN, 1);
            ambRow[p] = tid; ambCnt[p] = cnt;
            int c2 = 0;
            for (int k = 0; k < 32 && c2 < 16; k++)
                if (mergeS[base + k] <= lim) ambCand[p * 16 + c2++] = mergeI[base + k];
        }
    }
    __syncthreads();

    // ---- inline full-scan (rare rows), block-wide, exact reference chain ----
    {
        int nF = *fsN;
        float* zrow = (float*)(sm + RS_ZROW);
        float* rS = (float*)(sm + RS_RS);
        int*   rI = (int*)(sm + RS_RI);
        for (int f = 0; f < nF; f++) {
            int row = n0 + fsRow[f];
            const float* zr = z + (size_t)(row >> 12) * CS + (row & 4095);
            if (tid < 256) zrow[tid] = zr[(size_t)tid << 12];
            __syncthreads();
            float zn = g_znorm[row];
            float bs = 3.4e38f; int bi = 0x7fffffff;
            for (int j = tid; j < K_CODES; j += 512) {
                const float* cr = cb + (size_t)j * C_DIM;
                float dot = 0.0f;
                #pragma unroll 8
                for (int c = 0; c < C_DIM; c++) dot = fmaf(zrow[c], cr[c], dot);
                float s = __fadd_rn(__fadd_rn(zn, g_cnorm[j]), -2.0f * dot);
                if (s < bs || (s == bs && j < bi)) { bs = s; bi = j; }
            }
            rS[tid] = bs; rI[tid] = bi;
            __syncthreads();
            for (int off = 256; off > 0; off >>= 1) {
                if (tid < off) {
                    float s2 = rS[tid + off]; int i2 = rI[tid + off];
                    if (s2 < rS[tid] || (s2 == rS[tid] && i2 < rI[tid])) { rS[tid] = s2; rI[tid] = i2; }
                }
                __syncthreads();
            }
            if (tid == 0) { g_idx[row] = rI[0]; out_idx_f[row] = (float)rI[0]; }
            __syncthreads();
        }
    }

    // ---- inline ambiguous rescore (exact reference chain), warp-parallel ----
    {
        int nA = *ambN;
        for (int rec = w; rec < nA; rec += 16) {
            int row = n0 + ambRow[rec];
            int nc = ambCnt[rec];
            float s = 3.4e38f; int ci = 0x7fffffff;
            if (l < nc) {
                ci = ambCand[rec * 16 + l];
                const float* zr = z + (size_t)(row >> 12) * CS + (row & 4095);
                const float* cr = cb + (size_t)ci * C_DIM;
                float dot = 0.0f;
                #pragma unroll 8
                for (int c = 0; c < C_DIM; c++) dot = fmaf(zr[(size_t)c << 12], cr[c], dot);
                s = __fadd_rn(__fadd_rn(g_znorm[row], g_cnorm[ci]), -2.0f * dot);
            }
            #pragma unroll
            for (int off = 16; off > 0; off >>= 1) {
                float so = __shfl_down_sync(0xffffffffu, s, off);
                int   io = __shfl_down_sync(0xffffffffu, ci, off);
                if (so < s || (so == s && io < ci)) { s = so; ci = io; }
            }
            if (l == 0) { g_idx[row] = ci; out_idx_f[row] = (float)ci; }
        }
    }
}

// ---------- gather + loss ----------
__global__ void gather_loss_kernel(const float* __restrict__ z, const float* __restrict__ cb,
                                   float* __restrict__ out, float* __restrict__ loss) {
    int tid = threadIdx.x;
    int n = blockIdx.x * 256 + tid;
    int b = n >> 12, s = n & 4095;
    int ci = g_idx[n];
    const float* zr = z + (size_t)b * CS + s;
    float* orow = out + (size_t)b * CS + s;
    const float4* cr = (const float4*)(cb + (size_t)ci * C_DIM);

    float sum = 0.0f;
    #pragma unroll 4
    for (int c4 = 0; c4 < C_DIM / 4; c4++) {
        float4 q = cr[c4];
        size_t base = (size_t)(c4 * 4) * S_SPATIAL;
        float z0 = zr[base], z1 = zr[base + S_SPATIAL];
        float z2 = zr[base + 2 * S_SPATIAL], z3 = zr[base + 3 * S_SPATIAL];
        float d0 = __fadd_rn(q.x, -z0), d1 = __fadd_rn(q.y, -z1);
        float d2 = __fadd_rn(q.z, -z2), d3 = __fadd_rn(q.w, -z3);
        orow[base]                 = __fadd_rn(z0, d0);
        orow[base + S_SPATIAL]     = __fadd_rn(z1, d1);
        orow[base + 2 * S_SPATIAL] = __fadd_rn(z2, d2);
        orow[base + 3 * S_SPATIAL] = __fadd_rn(z3, d3);
        sum += d0 * d0 + d1 * d1 + d2 * d2 + d3 * d3;
    }
    __shared__ float wsum[8];
    #pragma unroll
    for (int off = 16; off > 0; off >>= 1) sum += __shfl_down_sync(0xffffffffu, sum, off);
    if ((tid & 31) == 0) wsum[tid >> 5] = sum;
    __syncthreads();
    if (tid == 0) {
        float t = 0.0f;
        #pragma unroll
        for (int w = 0; w < 8; w++) t += wsum[w];
        atomicAdd(loss, t * (2.0f / (float)(N_TOTAL * C_DIM)));
    }
}

extern "C" void kernel_launch(void* const* d_in, const int* in_sizes, int n_in,
                              void* d_out, int out_size) {
    (void)in_sizes; (void)n_in; (void)out_size;
    const float* z  = (const float*)d_in[0];
    const float* cb = (const float*)d_in[1];
    float* out  = (float*)d_out;
    float* loss = out + OUT_Z_ELEMS;
    float* idxf = out + OUT_Z_ELEMS + 1;

    cudaFuncSetAttribute(argmin_mma_kernel,
                         cudaFuncAttributeMaxDynamicSharedMemorySize, SMEM_BYTES);

    prep_kernel<<<832, 128>>>(z, cb, loss);
    argmin_mma_kernel<<<128, 512, SMEM_BYTES>>>(z, cb, idxf);
    gather_loss_kernel<<<128, 256>>>(z, cb, out, loss);
}

// round 17
// speedup vs baseline: 1.2330x; 1.2330x over previous
#include <cuda_runtime.h>
#include <cuda_bf16.h>
#include <cstdint>

#define N_TOTAL   32768
#define K_CODES   8192
#define C_DIM     256
#define S_SPATIAL 4096
#define CS        (C_DIM * S_SPATIAL)
#define OUT_Z_ELEMS 8388608

#define M_CTA   256
#define NCH     32
#define TAU     3.0e-4f
#define ROWB    272                  // bytes per padded int8 row
#define BBYTES  (NCH * ROWB)         // 8704

// score = zn + cn - 2*dot;  dot = acc / (20 * 127*8192)
#define SCONV   (-9.611847e-8f)      // -2 / 20807680

// dynamic smem map (bytes)
#define SM_CNS   0                   // float[4][32]
#define SM_A     1024                // 256 * 272 = 69632
#define SM_B     (SM_A + 69632)      // 4 buffers of 8704 = 34816
#define SMEM_BYTES (SM_B + 65536)    // merge region needs SM_B + 64KB = 136192

// resolve-phase smem layout (reuses dead A region)
#define RS_AMBN   (SM_A + 0)
#define RS_FSN    (SM_A + 4)
#define RS_FSROW  (SM_A + 16)
#define RS_AMBROW (SM_A + 1040)
#define RS_AMBCNT (SM_A + 2064)
#define RS_AMBCAND (SM_A + 3088)
#define RS_ZROW   (SM_A + 19472)
#define RS_RS     (SM_A + 20496)
#define RS_RI     (SM_A + 22544)

__device__ float g_znorm[N_TOTAL];
__device__ float g_cnorm[K_CODES];
__device__ int   g_idx[N_TOTAL];
__device__ __align__(16) signed char g_cb8[K_CODES * C_DIM];

// ---------- PTX helpers ----------
__device__ __forceinline__ uint32_t smem_u32(const void* p) {
    uint32_t a;
    asm("{ .reg .u64 t; cvta.to.shared.u64 t, %1; cvt.u32.u64 %0, t; }" : "=r"(a) : "l"(p));
    return a;
}
__device__ __forceinline__ void ldmx4(uint32_t* r, uint32_t addr) {
    asm volatile("ldmatrix.sync.aligned.m8n8.x4.shared.b16 {%0,%1,%2,%3}, [%4];"
                 : "=r"(r[0]), "=r"(r[1]), "=r"(r[2]), "=r"(r[3]) : "r"(addr));
}
__device__ __forceinline__ void mma16832s8(int* d, const uint32_t* a,
                                           uint32_t b0, uint32_t b1) {
    asm volatile("mma.sync.aligned.m16n8k32.row.col.s32.s8.s8.s32 "
                 "{%0,%1,%2,%3}, {%4,%5,%6,%7}, {%8,%9}, {%0,%1,%2,%3};"
                 : "+r"(d[0]), "+r"(d[1]), "+r"(d[2]), "+r"(d[3])
                 : "r"(a[0]), "r"(a[1]), "r"(a[2]), "r"(a[3]), "r"(b0), "r"(b1));
}
__device__ __forceinline__ void cpasync16(uint32_t dst, const void* src) {
    asm volatile("cp.async.ca.shared.global [%0], [%1], 16;" :: "r"(dst), "l"(src));
}
__device__ __forceinline__ void barsync(int id, int cnt) {
    asm volatile("bar.sync %0, %1;" :: "r"(id), "r"(cnt) : "memory");
}
__device__ __forceinline__ int q8(float v, float sc) {
    int q = __float2int_rn(v * sc);
    return max(-127, min(127, q));
}

// ---------- prep: loss init + norms + int8 codebook ----------
__global__ void prep_kernel(const float* __restrict__ z, const float* __restrict__ cb,
                            float* __restrict__ loss) {
    int bid = blockIdx.x, tid = threadIdx.x;
    if (bid < 256) {
        int n0 = bid * 128, b = n0 >> 12, s0 = n0 & 4095;
        const float* zr = z + (size_t)b * CS + s0 + tid;
        float sum = 0.0f;
        #pragma unroll 8
        for (int c = 0; c < C_DIM; c++) { float v = zr[(size_t)c * S_SPATIAL]; sum += v * v; }
        g_znorm[n0 + tid] = sum;
    } else if (bid < 320) {
        if (bid == 256 && tid == 0) *loss = 0.0f;
        int k = (bid - 256) * 128 + tid;
        const float4* cr = (const float4*)(cb + (size_t)k * C_DIM);
        float sum = 0.0f;
        #pragma unroll 8
        for (int i = 0; i < C_DIM / 4; i++) {
            float4 v = cr[i];
            sum += v.x * v.x + v.y * v.y + v.z * v.z + v.w * v.w;
        }
        g_cnorm[k] = sum;
    } else {
        // int8 codebook: scale 127*8192
        const float SC = 1040384.0f;
        int base = (bid - 320) * 4096;
        #pragma unroll 8
        for (int t = 0; t < 8; t++) {
            int i = base + t * 512 + tid * 4;
            float4 v = *(const float4*)(cb + i);
            uint32_t pk = (uint32_t)(q8(v.x, SC) & 255)
                        | ((uint32_t)(q8(v.y, SC) & 255) << 8)
                        | ((uint32_t)(q8(v.z, SC) & 255) << 16)
                        | ((uint32_t)(q8(v.w, SC) & 255) << 24);
            *(uint32_t*)(g_cb8 + i) = pk;
        }
    }
}

// ---------- main: int8 mma GEMM argmin + inline exact resolution ----------
__global__ void __launch_bounds__(512, 1)
argmin_mma_kernel(const float* __restrict__ z, const float* __restrict__ cb,
                  float* __restrict__ out_idx_f) {
    extern __shared__ char sm[];
    uint32_t smb = smem_u32(sm);
    int tid = threadIdx.x;
    int w = tid >> 5, l = tid & 31;
    int g  = w >> 3;                 // group 0: even chunks, group 1: odd chunks
    int wm = w & 7;                  // m-position (8 x 32 rows)
    int gl = tid & 255;
    int n0 = blockIdx.x * M_CTA;
    int b = n0 >> 12, s0 = n0 & 4095;
    float* cns = (float*)(sm + SM_CNS);

    // ---- fill A: 256 rows x 256 ch int8 (scale 20), padded rows of 272B ----
    {
        signed char* A = (signed char*)(sm + SM_A);
        int row = tid & 255;
        int ch0 = (tid >> 8) * 128;
        const float* zp = z + (size_t)b * CS + s0 + row;
        #pragma unroll 4
        for (int c = ch0; c < ch0 + 128; c += 4) {
            float v0 = zp[(size_t)c << 12];
            float v1 = zp[(size_t)(c + 1) << 12];
            float v2 = zp[(size_t)(c + 2) << 12];
            float v3 = zp[(size_t)(c + 3) << 12];
            uint32_t pk = (uint32_t)(q8(v0, 20.0f) & 255)
                        | ((uint32_t)(q8(v1, 20.0f) & 255) << 8)
                        | ((uint32_t)(q8(v2, 20.0f) & 255) << 16)
                        | ((uint32_t)(q8(v3, 20.0f) & 255) << 24);
            *(uint32_t*)(A + row * ROWB + c) = pk;
        }
    }

    float zn4[4];
    #pragma unroll
    for (int s = 0; s < 4; s++)
        zn4[s] = g_znorm[n0 + wm * 32 + (s >> 1) * 16 + (s & 1) * 8 + (l >> 2)];

    uint32_t aoff0 = smb + SM_A + (uint32_t)((wm * 32 + (l & 15)) * ROWB + (l >> 4) * 16);
    uint32_t aoff1 = aoff0 + 16u * ROWB;
    uint32_t bbase = smb + SM_B + (uint32_t)(g * 2 * BBYTES);
    uint32_t bofs0 = (uint32_t)((l & 15) * ROWB + (l >> 4) * 16);
    uint32_t bofs1 = bofs0 + 16u * ROWB;

    float bS[4][4]; int bI[4][4];
    #pragma unroll
    for (int s = 0; s < 4; s++)
        #pragma unroll
        for (int k = 0; k < 4; k++) { bS[s][k] = 3.4e38f; bI[s][k] = 0; }

    auto stage = [&](int k) {
        int chunk = g + 2 * k;
        const signed char* src = g_cb8 + (size_t)chunk * NCH * C_DIM;
        uint32_t bb = bbase + (uint32_t)((k & 1) * BBYTES);
        #pragma unroll
        for (int t = 0; t < 2; t++) {
            int idx = t * 256 + gl;            // 0..511
            int code = idx >> 4, seg = idx & 15;
            cpasync16(bb + (uint32_t)(code * ROWB + seg * 16),
                      src + (size_t)code * C_DIM + seg * 16);
        }
        if (gl < NCH) cns[(g * 2 + (k & 1)) * NCH + gl] = g_cnorm[chunk * NCH + gl];
        asm volatile("cp.async.commit_group;" ::: "memory");
    };

    stage(0);
    stage(1);
    __syncthreads();

    int barid = g + 1;
    for (int k = 0; k < 128; k++) {
        if (k < 126) { asm volatile("cp.async.wait_group 1;" ::: "memory"); }
        else         { asm volatile("cp.async.wait_group 0;" ::: "memory"); }
        barsync(barid, 256);

        // ---- GEMM: D[32 rows x 32 codes] per warp, k32 int8 ----
        int acc[2][4][4];
        #pragma unroll
        for (int mt = 0; mt < 2; mt++)
            #pragma unroll
            for (int nt = 0; nt < 4; nt++)
                #pragma unroll
                for (int c = 0; c < 4; c++) acc[mt][nt][c] = 0;

        uint32_t bsel = bbase + (uint32_t)((k & 1) * BBYTES);
        #pragma unroll
        for (int ks = 0; ks < 8; ks++) {
            uint32_t ka = (uint32_t)(ks * 32);
            uint32_t aF0[4], aF1[4], bL[4], bH[4];
            ldmx4(aF0, aoff0 + ka);
            ldmx4(aF1, aoff1 + ka);
            ldmx4(bL, bsel + bofs0 + ka);   // codes 0-15: {0-7 lo, 8-15 lo, 0-7 hi, 8-15 hi}
            ldmx4(bH, bsel + bofs1 + ka);   // codes 16-31
            mma16832s8(acc[0][0], aF0, bL[0], bL[2]);
            mma16832s8(acc[0][1], aF0, bL[1], bL[3]);
            mma16832s8(acc[0][2], aF0, bH[0], bH[2]);
            mma16832s8(acc[0][3], aF0, bH[1], bH[3]);
            mma16832s8(acc[1][0], aF1, bL[0], bL[2]);
            mma16832s8(acc[1][1], aF1, bL[1], bL[3]);
            mma16832s8(acc[1][2], aF1, bH[0], bH[2]);
            mma16832s8(acc[1][3], aF1, bH[1], bH[3]);
        }

        // ---- epilogue: scores + best-4 insert ----
        const float* cn = cns + (g * 2 + (k & 1)) * NCH;
        int j0 = (g + 2 * k) * NCH;
        #pragma unroll
        for (int nt = 0; nt < 4; nt++) {
            int col0 = nt * 8 + 2 * (l & 3);
            float2 cn2 = *(const float2*)&cn[col0];
            int id0 = j0 + col0;
            #pragma unroll
            for (int mt = 0; mt < 2; mt++) {
                #pragma unroll
                for (int c = 0; c < 4; c++) {
                    int slot = mt * 2 + (c >> 1);
                    float base = zn4[slot] + ((c & 1) ? cn2.y : cn2.x);
                    float s = fmaf(__int2float_rn(acc[mt][nt][c]), SCONV, base);
                    if (s < bS[slot][3]) {
                        int id = id0 + (c & 1);
                        #pragma unroll
                        for (int kk = 0; kk < 4; kk++) {
                            if (s < bS[slot][kk]) {
                                float ts = bS[slot][kk]; int ti = bI[slot][kk];
                                bS[slot][kk] = s; bI[slot][kk] = id;
                                s = ts; id = ti;
                            }
                        }
                    }
                }
            }
        }

        barsync(barid, 256);
        if (k + 2 < 128) stage(k + 2);
    }

    // ---- merge: per row 32 entries ----
    float* mergeS = (float*)(sm + SM_B);
    int*   mergeI = (int*)(sm + SM_B + 32768);
    __syncthreads();
    if (tid == 0) { *(int*)(sm + RS_AMBN) = 0; *(int*)(sm + RS_FSN) = 0; }
    #pragma unroll
    for (int s = 0; s < 4; s++) {
        int row = wm * 32 + (s >> 1) * 16 + (s & 1) * 8 + (l >> 2);
        int base = row * 32 + g * 16 + (l & 3) * 4;
        #pragma unroll
        for (int k = 0; k < 4; k++) { mergeS[base + k] = bS[s][k]; mergeI[base + k] = bI[s][k]; }
    }
    __syncthreads();

    // ---- classify ----
    int* ambN    = (int*)(sm + RS_AMBN);
    int* fsN     = (int*)(sm + RS_FSN);
    int* fsRow   = (int*)(sm + RS_FSROW);
    int* ambRow  = (int*)(sm + RS_AMBROW);
    int* ambCnt  = (int*)(sm + RS_AMBCNT);
    int* ambCand = (int*)(sm + RS_AMBCAND);
    if (tid < 256) {
        int base = tid * 32;
        float mn = 3.4e38f;
        #pragma unroll
        for (int k = 0; k < 32; k++) mn = fminf(mn, mergeS[base + k]);
        float lim = mn + TAU;
        bool fs = false;
        #pragma unroll
        for (int q = 0; q < 8; q++) if (mergeS[base + q * 4 + 3] <= lim) fs = true;
        int cnt = 0; float bs = 3.4e38f; int bi = 0x7fffffff;
        #pragma unroll
        for (int k = 0; k < 32; k++) {
            float s = mergeS[base + k]; int id = mergeI[base + k];
            if (s <= lim) cnt++;
            if (s < bs || (s == bs && id < bi)) { bs = s; bi = id; }
        }
        if (cnt > 16) fs = true;
        if (fs) {
            int p = atomicAdd(fsN, 1);
            fsRow[p] = tid;
        } else if (cnt == 1) {
            g_idx[n0 + tid] = bi;
            out_idx_f[n0 + tid] = (float)bi;
        } else {
            int p = atomicAdd(ambN, 1);
            ambRow[p] = tid; ambCnt[p] = cnt;
            int c2 = 0;
            for (int k = 0; k < 32 && c2 < 16; k++)
                if (mergeS[base + k] <= lim) ambCand[p * 16 + c2++] = mergeI[base + k];
        }
    }
    __syncthreads();

    // ---- inline full-scan (rare rows), exact reference chain ----
    {
        int nF = *fsN;
        float* zrow = (float*)(sm + RS_ZROW);
        float* rS = (float*)(sm + RS_RS);
        int*   rI = (int*)(sm + RS_RI);
        for (int f = 0; f < nF; f++) {
            int row = n0 + fsRow[f];
            const float* zr = z + (size_t)(row >> 12) * CS + (row & 4095);
            if (tid < 256) zrow[tid] = zr[(size_t)tid << 12];
            __syncthreads();
            float zn = g_znorm[row];
            float bs = 3.4e38f; int bi = 0x7fffffff;
            for (int j = tid; j < K_CODES; j += 512) {
                const float* cr = cb + (size_t)j * C_DIM;
                float dot = 0.0f;
                #pragma unroll 8
                for (int c = 0; c < C_DIM; c++) dot = fmaf(zrow[c], cr[c], dot);
                float s = __fadd_rn(__fadd_rn(zn, g_cnorm[j]), -2.0f * dot);
                if (s < bs || (s == bs && j < bi)) { bs = s; bi = j; }
            }
            rS[tid] = bs; rI[tid] = bi;
            __syncthreads();
            for (int off = 256; off > 0; off >>= 1) {
                if (tid < off) {
                    float s2 = rS[tid + off]; int i2 = rI[tid + off];
                    if (s2 < rS[tid] || (s2 == rS[tid] && i2 < rI[tid])) { rS[tid] = s2; rI[tid] = i2; }
                }
                __syncthreads();
            }
            if (tid == 0) { g_idx[row] = rI[0]; out_idx_f[row] = (float)rI[0]; }
            __syncthreads();
        }
    }

    // ---- inline ambiguous rescore (exact reference chain), warp-parallel ----
    {
        int nA = *ambN;
        for (int rec = w; rec < nA; rec += 16) {
            int row = n0 + ambRow[rec];
            int nc = ambCnt[rec];
            float s = 3.4e38f; int ci = 0x7fffffff;
            if (l < nc) {
                ci = ambCand[rec * 16 + l];
                const float* zr = z + (size_t)(row >> 12) * CS + (row & 4095);
                const float* cr = cb + (size_t)ci * C_DIM;
                float dot = 0.0f;
                #pragma unroll 8
                for (int c = 0; c < C_DIM; c++) dot = fmaf(zr[(size_t)c << 12], cr[c], dot);
                s = __fadd_rn(__fadd_rn(g_znorm[row], g_cnorm[ci]), -2.0f * dot);
            }
            #pragma unroll
            for (int off = 16; off > 0; off >>= 1) {
                float so = __shfl_down_sync(0xffffffffu, s, off);
                int   io = __shfl_down_sync(0xffffffffu, ci, off);
                if (so < s || (so == s && io < ci)) { s = so; ci = io; }
            }
            if (l == 0) { g_idx[row] = ci; out_idx_f[row] = (float)ci; }
        }
    }
}

// ---------- gather + loss ----------
__global__ void gather_loss_kernel(const float* __restrict__ z, const float* __restrict__ cb,
                                   float* __restrict__ out, float* __restrict__ loss) {
    int tid = threadIdx.x;
    int n = blockIdx.x * 256 + tid;
    int b = n >> 12, s = n & 4095;
    int ci = g_idx[n];
    const float* zr = z + (size_t)b * CS + s;
    float* orow = out + (size_t)b * CS + s;
    const float4* cr = (const float4*)(cb + (size_t)ci * C_DIM);

    float sum = 0.0f;
    #pragma unroll 4
    for (int c4 = 0; c4 < C_DIM / 4; c4++) {
        float4 q = cr[c4];
        size_t base = (size_t)(c4 * 4) * S_SPATIAL;
        float z0 = zr[base], z1 = zr[base + S_SPATIAL];
        float z2 = zr[base + 2 * S_SPATIAL], z3 = zr[base + 3 * S_SPATIAL];
        float d0 = __fadd_rn(q.x, -z0), d1 = __fadd_rn(q.y, -z1);
        float d2 = __fadd_rn(q.z, -z2), d3 = __fadd_rn(q.w, -z3);
        orow[base]                 = __fadd_rn(z0, d0);
        orow[base + S_SPATIAL]     = __fadd_rn(z1, d1);
        orow[base + 2 * S_SPATIAL] = __fadd_rn(z2, d2);
        orow[base + 3 * S_SPATIAL] = __fadd_rn(z3, d3);
        sum += d0 * d0 + d1 * d1 + d2 * d2 + d3 * d3;
    }
    __shared__ float wsum[8];
    #pragma unroll
    for (int off = 16; off > 0; off >>= 1) sum += __shfl_down_sync(0xffffffffu, sum, off);
    if ((tid & 31) == 0) wsum[tid >> 5] = sum;
    __syncthreads();
    if (tid == 0) {
        float t = 0.0f;
        #pragma unroll
        for (int w = 0; w < 8; w++) t += wsum[w];
        atomicAdd(loss, t * (2.0f / (float)(N_TOTAL * C_DIM)));
    }
}

extern "C" void kernel_launch(void* const* d_in, const int* in_sizes, int n_in,
                              void* d_out, int out_size) {
    (void)in_sizes; (void)n_in; (void)out_size;
    const float* z  = (const float*)d_in[0];
    const float* cb = (const float*)d_in[1];
    float* out  = (float*)d_out;
    float* loss = out + OUT_Z_ELEMS;
    float* idxf = out + OUT_Z_ELEMS + 1;

    cudaFuncSetAttribute(argmin_mma_kernel,
                         cudaFuncAttributeMaxDynamicSharedMemorySize, SMEM_BYTES);

    prep_kernel<<<832, 128>>>(z, cb, loss);
    argmin_mma_kernel<<<128, 512, SMEM_BYTES>>>(z, cb, idxf);
    gather_loss_kernel<<<128, 256>>>(z, cb, out, loss);
}